// round 5
// baseline (speedup 1.0000x reference)
#include <cuda_runtime.h>
#include <cuda_fp16.h>

#define BB   256
#define TT   512
#define HH   128
#define G4   512
#define IND  10
#define TRG  32

typedef unsigned long long u64;

// ---------------- packed f32x2 helpers ----------------
__device__ __forceinline__ void ffma2(u64& acc, u64 a, u64 b) {
    asm("fma.rn.f32x2 %0, %1, %2, %0;" : "+l"(acc) : "l"(a), "l"(b));
}
__device__ __forceinline__ u64 pk(float lo, float hi) {
    u64 d; asm("mov.b64 %0, {%1, %2};" : "=l"(d) : "f"(lo), "f"(hi)); return d;
}
__device__ __forceinline__ float psum(u64 a) {
    float x, y; asm("mov.b64 {%0, %1}, %2;" : "=f"(x), "=f"(y) : "l"(a));
    return x + y;
}
__device__ __forceinline__ u64 h2u64(unsigned int h2bits) {
    __half2 h = *reinterpret_cast<__half2*>(&h2bits);
    float2 f = __half22float2(h);
    u64 d; asm("mov.b64 %0, {%1, %2};" : "=l"(d) : "f"(f.x), "f"(f.y)); return d;
}

// ---------------- device-global scratch ----------------
// fp32 w_hh, rearranged for per-thread access. Thread t owns gates
//   gA = (t>>1) + (t&1)*256, gB = gA + 128   (pair (2u,2u+1) = unit u's i,f,g,o)
// g_wreg_f: k in [0,64), packed k-pairs:  [((L*2+which)*32 + (k>>1))*256 + t] as float2
// g_wsm_f:  k in [64,128), float4 blocks: [((L*2+which)*16 + ((k-64)>>2))*256 + t] as float4
__device__ float  g_wreg_f[2 * 2 * 32 * 256 * 2];
__device__ float  g_wsm_f[2 * 2 * 16 * 256 * 4];
__device__ __half g_wih1h[G4 * HH];               // fp16 blocked, for xgate1
__device__ float  g_h1[(size_t)BB * TT * HH];
__device__ float  g_xg1[(size_t)BB * TT * G4];
__device__ float  g_h2last[BB * HH];

__global__ void prep_kernel(const float* __restrict__ w_hh0,
                            const float* __restrict__ w_hh1,
                            const float* __restrict__ w_ih1)
{
    int idx = blockIdx.x * blockDim.x + threadIdx.x;   // 196608 threads
    if (idx < 131072) {
        int L = idx >> 16;
        int e = idx & 65535;
        int g = e >> 7;
        int k = e & 127;
        int which = (g >> 7) & 1;
        int t = ((g & 127) << 1) | (g >> 8);
        float v = (L ? w_hh1 : w_hh0)[e];
        if (k < 64)
            g_wreg_f[(((L * 2 + which) * 32 + (k >> 1)) * 256 + t) * 2 + (k & 1)] = v;
        else
            g_wsm_f[(((L * 2 + which) * 16 + ((k - 64) >> 2)) * 256 + t) * 4 + ((k - 64) & 3)] = v;
    } else {
        int e = idx - 131072;
        int g = e >> 7;
        int k = e & 127;
        int dst = ((k >> 3) << 12) + (g << 3) + (k & 7);
        g_wih1h[dst] = __float2half(w_ih1[e]);
    }
}

__device__ __forceinline__ float sigf(float x) {
    return 1.0f / (1.0f + __expf(-x));
}
__device__ __forceinline__ float tanhfast(float x) {
    return 2.0f / (1.0f + __expf(-2.0f * x)) - 1.0f;
}

// ---------------- LSTM recurrence ----------------
// 128 CTAs x 2 batch rows, 256 threads. Thread t: unit u = t>>1, half = t&1.
// half 0 -> gates (i_u, f_u); half 1 -> gates (g_u, o_u); both rows.
// All-fp32 math: k<64 weights in regs, k in [64,128) fp32 in smem.
// Gate exchange via shfl.xor(1); ONE barrier per step; h/x double-buffered.
// smem (bytes):
//   [0,131072)        w fp32, thread-indexed float4:  ws4[(which*16+c)*256 + t]
//   [131072,151552)   wih2 [10][2][256]     (layer0 only)
//   [151552,153600)   bias2 [2][256]        (layer0 only)
//   [153600,155648)   hs [2 buf][2 rows][128]
//   [155648,155904)   xs [2 buf][2 rows][16] (layer0 only)
#define LSTM_SMEM 155904

template<int LAYER>
__global__ void __launch_bounds__(256, 1) lstm_layer_kernel(
    const float* __restrict__ x,
    const float* __restrict__ w_ih,
    const float* __restrict__ b_ih,
    const float* __restrict__ b_hh)
{
    extern __shared__ char smem[];
    float* ws    = (float*)smem;
    float* wih2  = (float*)(smem + 131072);
    float* bias2 = (float*)(smem + 151552);
    float* hs    = (float*)(smem + 153600);
    float* xsb   = (float*)(smem + 155648);

    const int tid  = threadIdx.x;
    const int bb   = blockIdx.x;
    const int u    = tid >> 1;
    const int half = tid & 1;
    const int gA   = u + (half ? 256 : 0);
    const int gB   = gA + 128;

    // k<64 fp32 weights into registers (coalesced from prepped layout)
    u64 wreg0[32], wreg1[32];
    {
        const u64* wr = (const u64*)g_wreg_f;
        #pragma unroll
        for (int i = 0; i < 32; i++) {
            wreg0[i] = wr[((LAYER * 2 + 0) * 32 + i) * 256 + tid];
            wreg1[i] = wr[((LAYER * 2 + 1) * 32 + i) * 256 + tid];
        }
    }

    // k in [64,128) fp32 weights into smem (coalesced, thread-indexed)
    float4*       ws4 = (float4*)ws;
    const float4* gw4 = (const float4*)g_wsm_f;
    #pragma unroll
    for (int c = 0; c < 16; c++) {
        ws4[(0 * 16 + c) * 256 + tid] = gw4[((LAYER * 2 + 0) * 16 + c) * 256 + tid];
        ws4[(1 * 16 + c) * 256 + tid] = gw4[((LAYER * 2 + 1) * 16 + c) * 256 + tid];
    }

    if (LAYER == 0) {
        #pragma unroll
        for (int j = 0; j < IND; j++) {
            wih2[(j * 2 + 0) * 256 + tid] = w_ih[gA * IND + j];
            wih2[(j * 2 + 1) * 256 + tid] = w_ih[gB * IND + j];
        }
        bias2[tid]       = b_ih[gA] + b_hh[gA];
        bias2[256 + tid] = b_ih[gB] + b_hh[gB];
    }
    hs[tid] = 0.0f;          // zero h buffer 0

    float c0 = 0.0f, c1 = 0.0f;   // cell state for unit u, rows 0/1 (pair-redundant)

    // prefetch t=0 step inputs
    float xgA0 = 0.0f, xgA1 = 0.0f, xgB0 = 0.0f, xgB1 = 0.0f;
    int xr = 0, xj = 0;
    if (LAYER == 0) {
        if (tid < 2 * IND) {
            xr = tid / IND; xj = tid - xr * IND;
            xsb[xr * 16 + xj] = x[(size_t)(2 * bb + xr) * (TT * IND) + xj];
        }
    } else {
        const float* p0 = g_xg1 + ((size_t)(2 * bb + 0) * TT + 0) * G4;
        const float* p1 = g_xg1 + ((size_t)(2 * bb + 1) * TT + 0) * G4;
        xgA0 = p0[gA]; xgB0 = p0[gB];
        xgA1 = p1[gA]; xgB1 = p1[gB];
    }
    __syncthreads();

    for (int t = 0; t < TT; t++) {
        const int par = t & 1;
        const ulonglong2* curv = (const ulonglong2*)(hs + par * 256);
        float*            nxt  = hs + (par ^ 1) * 256;
        const float*      xs   = xsb + par * 32;
        float*            xsn  = xsb + (par ^ 1) * 32;

        // [A] prefetch next step's inputs
        float nx = 0.0f, nA0 = 0.0f, nA1 = 0.0f, nB0 = 0.0f, nB1 = 0.0f;
        if (LAYER == 0) {
            if (tid < 2 * IND && t + 1 < TT)
                nx = x[(size_t)(2 * bb + xr) * (TT * IND) + (size_t)(t + 1) * IND + xj];
        } else {
            if (t + 1 < TT) {
                const float* p0 = g_xg1 + ((size_t)(2 * bb + 0) * TT + (t + 1)) * G4;
                const float* p1 = g_xg1 + ((size_t)(2 * bb + 1) * TT + (t + 1)) * G4;
                nA0 = p0[gA]; nB0 = p0[gB];
                nA1 = p1[gA]; nB1 = p1[gB];
            }
        }

        // [B] initial scalar part
        float iA0, iA1, iB0, iB1;     // gate A/B, rows 0/1
        if (LAYER == 0) {
            float bvA = bias2[tid], bvB = bias2[256 + tid];
            iA0 = bvA; iA1 = bvA; iB0 = bvB; iB1 = bvB;
            #pragma unroll
            for (int j = 0; j < IND; j++) {
                float wAj = wih2[j * 512 + tid];
                float wBj = wih2[j * 512 + 256 + tid];
                float x0 = xs[j], x1 = xs[16 + j];
                iA0 = fmaf(x0, wAj, iA0);
                iA1 = fmaf(x1, wAj, iA1);
                iB0 = fmaf(x0, wBj, iB0);
                iB1 = fmaf(x1, wBj, iB1);
            }
        } else {
            iA0 = xgA0; iA1 = xgA1; iB0 = xgB0; iB1 = xgB1;
        }

        u64 aA0a = pk(iA0, 0.0f), aA0b = pk(0.0f, 0.0f);
        u64 aA1a = pk(iA1, 0.0f), aA1b = pk(0.0f, 0.0f);
        u64 aB0a = pk(iB0, 0.0f), aB0b = pk(0.0f, 0.0f);
        u64 aB1a = pk(iB1, 0.0f), aB1b = pk(0.0f, 0.0f);

        // k in [0,64): register weights (fp32 exact)
        #pragma unroll
        for (int i = 0; i < 16; i++) {
            ulonglong2 h0 = curv[i];        // row0, floats 4i..4i+3
            ulonglong2 h1 = curv[32 + i];   // row1
            ffma2(aA0a, h0.x, wreg0[2 * i]);
            ffma2(aA0b, h0.y, wreg0[2 * i + 1]);
            ffma2(aA1a, h1.x, wreg0[2 * i]);
            ffma2(aA1b, h1.y, wreg0[2 * i + 1]);
            ffma2(aB0a, h0.x, wreg1[2 * i]);
            ffma2(aB0b, h0.y, wreg1[2 * i + 1]);
            ffma2(aB1a, h1.x, wreg1[2 * i]);
            ffma2(aB1b, h1.y, wreg1[2 * i + 1]);
        }

        // k in [64,128): fp32 smem weights (conflict-free, zero conversions)
        const ulonglong2* wsu = (const ulonglong2*)ws;
        #pragma unroll
        for (int c = 0; c < 16; c++) {
            ulonglong2 wA = wsu[(0 * 16 + c) * 256 + tid];
            ulonglong2 wB = wsu[(1 * 16 + c) * 256 + tid];
            ulonglong2 h0 = curv[16 + c];
            ulonglong2 h1 = curv[48 + c];
            ffma2(aA0a, h0.x, wA.x);
            ffma2(aA0b, h0.y, wA.y);
            ffma2(aA1a, h1.x, wA.x);
            ffma2(aA1b, h1.y, wA.y);
            ffma2(aB0a, h0.x, wB.x);
            ffma2(aB0b, h0.y, wB.y);
            ffma2(aB1a, h1.x, wB.x);
            ffma2(aB1b, h1.y, wB.y);
        }

        float vA0 = psum(aA0a) + psum(aA0b);
        float vA1 = psum(aA1a) + psum(aA1b);
        float vB0 = psum(aB0a) + psum(aB0b);
        float vB1 = psum(aB1a) + psum(aB1b);

        // exchange with pair lane (unit u's other two gates)
        float pA0 = __shfl_xor_sync(0xffffffffu, vA0, 1);
        float pA1 = __shfl_xor_sync(0xffffffffu, vA1, 1);
        float pB0 = __shfl_xor_sync(0xffffffffu, vB0, 1);
        float pB1 = __shfl_xor_sync(0xffffffffu, vB1, 1);

        float gi0, gf0, gg0, go0, gi1, gf1, gg1, go1;
        if (half == 0) {
            gi0 = vA0; gf0 = vB0; gg0 = pA0; go0 = pB0;
            gi1 = vA1; gf1 = vB1; gg1 = pA1; go1 = pB1;
        } else {
            gi0 = pA0; gf0 = pB0; gg0 = vA0; go0 = vB0;
            gi1 = pA1; gf1 = pB1; gg1 = vA1; go1 = vB1;
        }

        c0 = sigf(gf0) * c0 + sigf(gi0) * tanhfast(gg0);
        c1 = sigf(gf1) * c1 + sigf(gi1) * tanhfast(gg1);
        float h0n = sigf(go0) * tanhfast(c0);
        float h1n = sigf(go1) * tanhfast(c1);

        if (half == 0) nxt[u]       = h0n;
        else           nxt[128 + u] = h1n;

        if (LAYER == 0) {
            if (half == 0)
                g_h1[((size_t)(2 * bb + 0) * TT + t) * HH + u] = h0n;
            else
                g_h1[((size_t)(2 * bb + 1) * TT + t) * HH + u] = h1n;
        } else if (t == TT - 1) {
            g_h2last[(2 * bb + half) * HH + u] = half ? h1n : h0n;
        }

        if (LAYER == 0) {
            if (tid < 2 * IND) xsn[xr * 16 + xj] = nx;
        } else {
            xgA0 = nA0; xgA1 = nA1; xgB0 = nB0; xgB1 = nB1;
        }
        __syncthreads();
    }
}

// ---------------- layer-1 input projection GEMM ----------------
// 256 threads, thread = gates (tid, tid+256), 32 rows per CTA.
#define XG_SMEM (131072 + TRG * HH * 4)

__global__ void __launch_bounds__(256, 1) xgate1_kernel(
    const float* __restrict__ b_ih1, const float* __restrict__ b_hh1)
{
    extern __shared__ char smem[];
    __half* wsm = (__half*)smem;
    float*  h_s = (float*)(smem + 131072);

    const int tid = threadIdx.x;
    const int g0t = tid;
    const int g1t = tid + 256;

    uint4*       wsm4 = (uint4*)wsm;
    const uint4* gw4  = (const uint4*)g_wih1h;
    #pragma unroll
    for (int i = 0; i < 16; i++) {
        wsm4[i * 512 + g0t] = gw4[i * 512 + g0t];
        wsm4[i * 512 + g1t] = gw4[i * 512 + g1t];
    }

    const size_t base = (size_t)blockIdx.x * TRG * HH;
    float4*       h_s4 = (float4*)h_s;
    const float4* src4 = (const float4*)(g_h1 + base);
    #pragma unroll
    for (int i = 0; i < (TRG * HH / 4) / 256; i++)
        h_s4[i * 256 + tid] = src4[i * 256 + tid];
    __syncthreads();

    float bvA = b_ih1[g0t] + b_hh1[g0t];
    float bvB = b_ih1[g1t] + b_hh1[g1t];
    u64 accA[TRG], accB[TRG];
    #pragma unroll
    for (int r = 0; r < TRG; r++) { accA[r] = pk(bvA, 0.0f); accB[r] = pk(bvB, 0.0f); }

    #pragma unroll 1
    for (int c = 0; c < 16; c++) {
        uint4 wpA = wsm4[c * 512 + g0t];
        uint4 wpB = wsm4[c * 512 + g1t];
        u64 wA0 = h2u64(wpA.x), wA1 = h2u64(wpA.y);
        u64 wA2 = h2u64(wpA.z), wA3 = h2u64(wpA.w);
        u64 wB0 = h2u64(wpB.x), wB1 = h2u64(wpB.y);
        u64 wB2 = h2u64(wpB.z), wB3 = h2u64(wpB.w);
        #pragma unroll
        for (int r = 0; r < TRG; r++) {
            ulonglong2 ha = *(const ulonglong2*)(h_s + r * HH + c * 8);
            ulonglong2 hb = *(const ulonglong2*)(h_s + r * HH + c * 8 + 4);
            ffma2(accA[r], ha.x, wA0);
            ffma2(accA[r], ha.y, wA1);
            ffma2(accA[r], hb.x, wA2);
            ffma2(accA[r], hb.y, wA3);
            ffma2(accB[r], ha.x, wB0);
            ffma2(accB[r], ha.y, wB1);
            ffma2(accB[r], hb.x, wB2);
            ffma2(accB[r], hb.y, wB3);
        }
    }

    #pragma unroll
    for (int r = 0; r < TRG; r++) {
        g_xg1[((size_t)blockIdx.x * TRG + r) * G4 + g0t] = psum(accA[r]);
        g_xg1[((size_t)blockIdx.x * TRG + r) * G4 + g1t] = psum(accB[r]);
    }
}

// ---------------- final FC ----------------
__global__ void fc_kernel(const float* __restrict__ fc_w,
                          const float* __restrict__ fc_b,
                          float* __restrict__ out)
{
    int b = threadIdx.x;
    const float* hrow = g_h2last + b * HH;
    #pragma unroll
    for (int c = 0; c < 10; c++) {
        float acc = fc_b[c];
        #pragma unroll
        for (int k = 0; k < HH; k++)
            acc = fmaf(hrow[k], fc_w[c * HH + k], acc);
        out[b * 10 + c] = acc;
    }
}

extern "C" void kernel_launch(void* const* d_in, const int* in_sizes, int n_in,
                              void* d_out, int out_size)
{
    const float* x     = (const float*)d_in[0];
    const float* w_ih0 = (const float*)d_in[1];
    const float* w_hh0 = (const float*)d_in[2];
    const float* b_ih0 = (const float*)d_in[3];
    const float* b_hh0 = (const float*)d_in[4];
    const float* w_ih1 = (const float*)d_in[5];
    const float* w_hh1 = (const float*)d_in[6];
    const float* b_ih1 = (const float*)d_in[7];
    const float* b_hh1 = (const float*)d_in[8];
    const float* fc_w  = (const float*)d_in[9];
    const float* fc_b  = (const float*)d_in[10];
    float* out = (float*)d_out;

    cudaFuncSetAttribute(lstm_layer_kernel<0>,
                         cudaFuncAttributeMaxDynamicSharedMemorySize, LSTM_SMEM);
    cudaFuncSetAttribute(lstm_layer_kernel<1>,
                         cudaFuncAttributeMaxDynamicSharedMemorySize, LSTM_SMEM);
    cudaFuncSetAttribute(xgate1_kernel,
                         cudaFuncAttributeMaxDynamicSharedMemorySize, XG_SMEM);

    prep_kernel<<<768, 256>>>(w_hh0, w_hh1, w_ih1);
    lstm_layer_kernel<0><<<BB / 2, 256, LSTM_SMEM>>>(x, w_ih0, b_ih0, b_hh0);
    xgate1_kernel<<<(BB * TT) / TRG, 256, XG_SMEM>>>(b_ih1, b_hh1);
    lstm_layer_kernel<1><<<BB / 2, 256, LSTM_SMEM>>>(nullptr, nullptr, nullptr, nullptr);
    fc_kernel<<<1, 256>>>(fc_w, fc_b, out);
}